// round 16
// baseline (speedup 1.0000x reference)
#include <cuda_runtime.h>

// Round-to-nearest-even magic constant (1.5 * 2^23).
#define RMAGIC 12582912.0f
#define NLEV_M1 255.0f

// -------------------------------------------------------------------------
// Core: out = clip(round(x/d), -zp, 255-zp) * d, with L = {1/d, d, -zp, 255-zp}
// -------------------------------------------------------------------------
__device__ __forceinline__ float q_core(float xv, float4 L)
{
    float t  = __fmaf_rn(xv, L.x, RMAGIC);   // x*(1/d) + magic (RNE round)
    float r  = __fadd_rn(t, -RMAGIC);        // round-half-even(x/d)
    r = fminf(fmaxf(r, L.z), L.w);           // clip(round, -zp, 255-zp)
    return r * L.y;                          // * d
}

// EXACT group id via sign accumulation:
//   diff = xa - m_k: near the threshold Sterbenz makes the FADD exact, so the
//   sign (with +0 on equality) is the exact predicate (xa >= m_k <-> diff >= +0,
//   and bits(+0) = 0 has sign bit clear). Far from threshold the sign is
//   trivially correct (|diff| >= 0.25 >> rounding).
//   __mulhi(bits(diff), 2) = -1 iff sign bit set, else 0  (single IMAD.HI).
//   c' = sum in [-GM, 0]; true count = GM + c', folded into the LUT pointer.
template <int GM>
__device__ __forceinline__ float q1(float xv, const float* __restrict__ m,
                                    const float4* __restrict__ lutc)
{
    float xa = fabsf(xv);
    int c = 0;
#pragma unroll
    for (int k = 0; k < GM; k++) {
        float diff = __fadd_rn(xa, -m[k]);                 // FADD (exact sign)
        c += __mulhi(__float_as_int(diff), 2);             // IMAD.HI: -1 if neg
    }
    return q_core(xv, lutc[c]);              // lutc = lut + GM; c in [-GM, 0]
}

template <int GM>
__device__ __forceinline__ float4 q4(float4 v, const float* __restrict__ m,
                                     const float4* __restrict__ lutc)
{
    float4 o;
    o.x = q1<GM>(v.x, m, lutc);
    o.y = q1<GM>(v.y, m, lutc);
    o.z = q1<GM>(v.z, m, lutc);
    o.w = q1<GM>(v.w, m, lutc);
    return o;
}

// -------------------------------------------------------------------------
// Main vectorized kernel (GM = G-1 medians in registers).
// (clip(sum_{i<G}, 0, G-1) == sum_{i<G-1} for sorted medians.)
// -------------------------------------------------------------------------
template <int GM>
__global__ void __launch_bounds__(256, 4) quant_vec_kernel(
    const float4* __restrict__ x,
    const float* __restrict__ med,
    const float* __restrict__ del,
    const float* __restrict__ zp,
    float4* __restrict__ out,
    int n4)
{
    __shared__ float4 slut[GM + 1];
    if (threadIdx.x <= GM) {
        float d = del[threadIdx.x];
        float z = zp[threadIdx.x];
        slut[threadIdx.x] = make_float4(__frcp_rn(d), d, -z, NLEV_M1 - z);
    }
    __syncthreads();

    float m[GM];
#pragma unroll
    for (int k = 0; k < GM; k++) m[k] = __ldg(med + k);

    const float4* lutc = slut + GM;          // rebias: index in [-GM, 0]

    const int stride = gridDim.x * blockDim.x;
    const int i0 = blockIdx.x * blockDim.x + threadIdx.x;
    const int per = stride * 4;
    const int nmain = (n4 / per) * per;

    for (int i = i0; i < nmain; i += per) {
        float4 v0 = __ldg(x + i);
        float4 v1 = __ldg(x + i + stride);
        float4 v2 = __ldg(x + i + 2 * stride);
        float4 v3 = __ldg(x + i + 3 * stride);
        out[i]              = q4<GM>(v0, m, lutc);
        out[i + stride]     = q4<GM>(v1, m, lutc);
        out[i + 2 * stride] = q4<GM>(v2, m, lutc);
        out[i + 3 * stride] = q4<GM>(v3, m, lutc);
    }
    for (int i = nmain + i0; i < n4; i += stride)
        out[i] = q4<GM>(__ldg(x + i), m, lutc);
}

// -------------------------------------------------------------------------
// Generic scalar fallback (runtime G, and n%4 tail). Exact compares.
// -------------------------------------------------------------------------
__global__ void quant_scalar_kernel(
    const float* __restrict__ x,
    const float* __restrict__ med,
    const float* __restrict__ del,
    const float* __restrict__ zp,
    float* __restrict__ out,
    int n, int G, int start)
{
    __shared__ float smed[128];
    __shared__ float4 slut[128];
    for (int t = threadIdx.x; t < G; t += blockDim.x) {
        smed[t] = med[t];
        float d = del[t];
        float z = zp[t];
        slut[t] = make_float4(__frcp_rn(d), d, -z, NLEV_M1 - z);
    }
    __syncthreads();

    const int stride = gridDim.x * blockDim.x;
    for (int i = start + blockIdx.x * blockDim.x + threadIdx.x; i < n; i += stride) {
        float xv = x[i];
        int c = 0;
        for (int k = 0; k < G; k++) c += (fabsf(xv) >= smed[k]) ? 1 : 0;
        if (c > G - 1) c = G - 1;
        out[i] = q_core(xv, slut[c]);
    }
}

// -------------------------------------------------------------------------
// Launch
// -------------------------------------------------------------------------
extern "C" void kernel_launch(void* const* d_in, const int* in_sizes, int n_in,
                              void* d_out, int out_size)
{
    const float* x   = (const float*)d_in[0];
    const float* med = (const float*)d_in[1];
    const float* del = (const float*)d_in[2];
    const float* zp  = (const float*)d_in[3];
    float* out = (float*)d_out;

    const int n = in_sizes[0];
    const int G = in_sizes[1];

    if (G == 10) {
        const int n4 = n / 4;
        if (n4 > 0) {
            int blocks = 4736;                 // 32 * 148 SMs
            int maxb = (n4 + 255) / 256;
            if (blocks > maxb) blocks = maxb;
            quant_vec_kernel<9><<<blocks, 256>>>(
                (const float4*)x, med, del, zp, (float4*)out, n4);
        }
        const int rem_start = (n / 4) * 4;
        if (rem_start < n) {
            quant_scalar_kernel<<<1, 256>>>(x, med, del, zp, out, n, G, rem_start);
        }
    } else {
        int blocks = (n + 255) / 256;
        if (blocks > 8192) blocks = 8192;
        if (blocks < 1) blocks = 1;
        quant_scalar_kernel<<<blocks, 256>>>(x, med, del, zp, out, n, G, 0);
    }
}